// round 1
// baseline (speedup 1.0000x reference)
#include <cuda_runtime.h>
#include <cstdint>

#define MTOK  8192      // B*S = 4*2048 tokens
#define D_    768
#define NCODE 16384
#define THRv  100.0f

#define MT 64
#define NT 64
#define KT 16
#define NSPLIT 8
#define NCHUNK (NCODE / NSPLIT)   // 2048
#define MPAD (MT + 4)             // keep float4 alignment (272B row), soften store conflicts

// Scratch (no allocations allowed)
__device__ float g_c2[NCODE];
__device__ float g_x2[MTOK];
__device__ unsigned long long g_key[MTOK];

// ---------------------------------------------------------------------------
// c2[n] = sum codes[n]^2  (inf if inactive). Handles active stored as uint8 OR int32.
// ---------------------------------------------------------------------------
__global__ void prep_c2_kernel(const float* __restrict__ codes,
                               const unsigned char* __restrict__ act8) {
    int n = blockIdx.x;
    const float* row = codes + (size_t)n * D_;
    float s = 0.f;
    for (int d = threadIdx.x; d < D_; d += 128) { float v = row[d]; s += v * v; }
    __shared__ float red[128];
    red[threadIdx.x] = s;
    __syncthreads();
    for (int off = 64; off; off >>= 1) {
        if (threadIdx.x < off) red[threadIdx.x] += red[threadIdx.x + off];
        __syncthreads();
    }
    if (threadIdx.x == 0) {
        // Detect int32-encoded bool: all-true int32 array starts [1,0,0,0]
        bool int32mode = (act8[0] == 1) && (act8[1] == 0) && (act8[2] == 0) && (act8[3] == 0);
        bool a;
        if (int32mode) a = (((const int*)act8)[n] != 0);
        else           a = (act8[n] != 0);
        g_c2[n] = a ? red[0] : __int_as_float(0x7f800000);  // +inf if inactive
    }
}

// ---------------------------------------------------------------------------
// x2[t] = sum x[t]^2 ; init packed min keys
// ---------------------------------------------------------------------------
__global__ void prep_x2_kernel(const float* __restrict__ x) {
    int t = blockIdx.x;
    const float* row = x + (size_t)t * D_;
    float s = 0.f;
    for (int d = threadIdx.x; d < D_; d += 128) { float v = row[d]; s += v * v; }
    __shared__ float red[128];
    red[threadIdx.x] = s;
    __syncthreads();
    for (int off = 64; off; off >>= 1) {
        if (threadIdx.x < off) red[threadIdx.x] += red[threadIdx.x + off];
        __syncthreads();
    }
    if (threadIdx.x == 0) {
        g_x2[t] = red[0];
        g_key[t] = 0xFFFFFFFFFFFFFFFFULL;
    }
}

// ---------------------------------------------------------------------------
// Tiled GEMM (x @ codes^T) with fused running-min of (c2[n] - 2*dot) per token.
// Block: 256 threads = 16x16, each computes a 4x4 micro-tile of the 64x64 tile.
// ---------------------------------------------------------------------------
__device__ __forceinline__ unsigned float_to_ordered(float f) {
    unsigned b = __float_as_uint(f);
    return (b & 0x80000000u) ? ~b : (b | 0x80000000u);
}

__global__ __launch_bounds__(256) void gemm_min_kernel(const float* __restrict__ x,
                                                       const float* __restrict__ codes) {
    __shared__ __align__(16) float As[KT][MPAD];
    __shared__ __align__(16) float Bs[KT][MPAD];

    const int mBase = blockIdx.x * MT;
    const int nChunkBase = blockIdx.y * NCHUNK;
    const int tid = threadIdx.x;
    const int tx = tid & 15;        // 0..15 -> column group
    const int ty = tid >> 4;        // 0..15 -> row group
    const int lrow = tid >> 2;      // 0..63 loader row
    const int lk   = (tid & 3) * 4; // 0,4,8,12 loader k offset (float4)

    float bestv[4];
    int   besti[4];
#pragma unroll
    for (int i = 0; i < 4; i++) { bestv[i] = __int_as_float(0x7f800000); besti[i] = 0; }

    const float* aRowPtr = x + (size_t)(mBase + lrow) * D_ + lk;

    for (int nt = 0; nt < NCHUNK; nt += NT) {
        const int nBase = nChunkBase + nt;
        const float* bRowPtr = codes + (size_t)(nBase + lrow) * D_ + lk;

        float acc[4][4];
#pragma unroll
        for (int i = 0; i < 4; i++)
#pragma unroll
            for (int j = 0; j < 4; j++) acc[i][j] = 0.f;

        for (int kb = 0; kb < D_; kb += KT) {
            float4 av = *(const float4*)(aRowPtr + kb);
            float4 bv = *(const float4*)(bRowPtr + kb);
            __syncthreads();   // previous tile fully consumed
            As[lk + 0][lrow] = av.x; As[lk + 1][lrow] = av.y;
            As[lk + 2][lrow] = av.z; As[lk + 3][lrow] = av.w;
            Bs[lk + 0][lrow] = bv.x; Bs[lk + 1][lrow] = bv.y;
            Bs[lk + 2][lrow] = bv.z; Bs[lk + 3][lrow] = bv.w;
            __syncthreads();
#pragma unroll
            for (int k = 0; k < KT; k++) {
                float4 a = *(const float4*)&As[k][ty * 4];
                float4 b = *(const float4*)&Bs[k][tx * 4];
                acc[0][0] += a.x * b.x; acc[0][1] += a.x * b.y;
                acc[0][2] += a.x * b.z; acc[0][3] += a.x * b.w;
                acc[1][0] += a.y * b.x; acc[1][1] += a.y * b.y;
                acc[1][2] += a.y * b.z; acc[1][3] += a.y * b.w;
                acc[2][0] += a.z * b.x; acc[2][1] += a.z * b.y;
                acc[2][2] += a.z * b.z; acc[2][3] += a.z * b.w;
                acc[3][0] += a.w * b.x; acc[3][1] += a.w * b.y;
                acc[3][2] += a.w * b.z; acc[3][3] += a.w * b.w;
            }
        }

        // Fused epilogue: score = c2[n] - 2*dot ; running per-row min.
        float c2v[4];
#pragma unroll
        for (int j = 0; j < 4; j++) c2v[j] = g_c2[nBase + tx * 4 + j];
#pragma unroll
        for (int i = 0; i < 4; i++) {
#pragma unroll
            for (int j = 0; j < 4; j++) {
                float s = fmaf(-2.0f, acc[i][j], c2v[j]);
                int n = nBase + tx * 4 + j;
                if (s < bestv[i]) { bestv[i] = s; besti[i] = n; }
            }
        }
    }

    // Reduce across the 16 tx lanes owning the same rows, then one atomic per row.
#pragma unroll
    for (int i = 0; i < 4; i++) {
        unsigned long long key =
            (((unsigned long long)float_to_ordered(bestv[i])) << 32) | (unsigned)besti[i];
#pragma unroll
        for (int off = 8; off > 0; off >>= 1) {
            unsigned long long o = __shfl_down_sync(0xffffffffu, key, off, 16);
            if (o < key) key = o;
        }
        if (tx == 0) atomicMin(&g_key[mBase + ty * 4 + i], key);
    }
}

// ---------------------------------------------------------------------------
// Unpack + threshold. Output layout: [idx_out (8192) | dmin (8192)] as float32.
// ---------------------------------------------------------------------------
__global__ void finalize_kernel(float* __restrict__ out, int out_size) {
    int t = blockIdx.x * blockDim.x + threadIdx.x;
    if (t >= MTOK) return;
    unsigned long long key = g_key[t];
    unsigned u = (unsigned)(key >> 32);
    unsigned b = (u & 0x80000000u) ? (u & 0x7fffffffu) : ~u;
    float s = __uint_as_float(b);
    int idx = (int)(key & 0xffffffffu);
    float dmin = g_x2[t] + s;
    int idx_out = (dmin <= THRv) ? idx : -1;
    out[t] = (float)idx_out;
    if (out_size >= 2 * MTOK) out[MTOK + t] = dmin;
}

// ---------------------------------------------------------------------------
extern "C" void kernel_launch(void* const* d_in, const int* in_sizes, int n_in,
                              void* d_out, int out_size) {
    const float* x     = (const float*)d_in[0];
    const float* codes = (const float*)d_in[1];
    const unsigned char* act = (const unsigned char*)d_in[2];

    prep_c2_kernel<<<NCODE, 128>>>(codes, act);
    prep_x2_kernel<<<MTOK, 128>>>(x);
    gemm_min_kernel<<<dim3(MTOK / MT, NSPLIT), 256>>>(x, codes);
    finalize_kernel<<<(MTOK + 255) / 256, 256>>>((float*)d_out, out_size);
}

// round 7
// speedup vs baseline: 1.8910x; 1.8910x over previous
#include <cuda_runtime.h>
#include <mma.h>
#include <cstdint>

using namespace nvcuda;

#define MTOK  8192
#define D_    768
#define NCODE 16384
#define THRv  100.0f

#define BM 128
#define BN 128
#define BK 32
#define NSPLIT 16
#define NCHUNK (NCODE / NSPLIT)       // 1024
#define NTILES (NCHUNK / BN)          // 8
#define NKSTEP (D_ / BK)              // 24
#define SROWF  36                     // padded fp32 smem row (floats)
#define NCAND  (NSPLIT * NTILES)      // 128 candidates per token

// Scratch (static device memory — allocations are forbidden)
__device__ float g_c2[NCODE];
__device__ float g_x2[MTOK];
__device__ unsigned long long g_cand[MTOK * NCAND];

// ---------------------------------------------------------------------------
// c2[n] = sum codes[n]^2 (exact fp32), +inf if inactive (uint8 or int32 bool).
__global__ void prep_c2_kernel(const float* __restrict__ codes,
                               const unsigned char* __restrict__ act8) {
    int n = blockIdx.x;
    const float* row = codes + (size_t)n * D_;
    float s = 0.f;
    for (int d = threadIdx.x; d < D_; d += 128) { float v = row[d]; s += v * v; }
    __shared__ float red[128];
    red[threadIdx.x] = s;
    __syncthreads();
    for (int off = 64; off; off >>= 1) {
        if (threadIdx.x < off) red[threadIdx.x] += red[threadIdx.x + off];
        __syncthreads();
    }
    if (threadIdx.x == 0) {
        bool int32mode = (act8[0] == 1) && (act8[1] == 0) && (act8[2] == 0) && (act8[3] == 0);
        bool a = int32mode ? (((const int*)act8)[n] != 0) : (act8[n] != 0);
        g_c2[n] = a ? red[0] : __int_as_float(0x7f800000);
    }
}

__global__ void prep_x2_kernel(const float* __restrict__ x) {
    int t = blockIdx.x;
    const float* row = x + (size_t)t * D_;
    float s = 0.f;
    for (int d = threadIdx.x; d < D_; d += 128) { float v = row[d]; s += v * v; }
    __shared__ float red[128];
    red[threadIdx.x] = s;
    __syncthreads();
    for (int off = 64; off; off >>= 1) {
        if (threadIdx.x < off) red[threadIdx.x] += red[threadIdx.x + off];
        __syncthreads();
    }
    if (threadIdx.x == 0) g_x2[t] = red[0];
}

__global__ void init_cand_kernel() {
    int i = blockIdx.x * blockDim.x + threadIdx.x;
    if (i < MTOK * NCAND) g_cand[i] = 0xFFFFFFFFFFFFFFFFULL;
}

// ---------------------------------------------------------------------------
__device__ __forceinline__ unsigned float_to_ordered(float f) {
    unsigned b = __float_as_uint(f);
    return (b & 0x80000000u) ? ~b : (b | 0x80000000u);
}

// ---------------------------------------------------------------------------
// Selection GEMM: tf32 WMMA (16x16x8) DIRECT from fp32 inputs (no bf16 staging).
// Single-stage smem; per-token per-TILE winner nominated for exact rescoring.
// ---------------------------------------------------------------------------
__global__ __launch_bounds__(256) void gemm_tf32_kernel(const float* __restrict__ x,
                                                        const float* __restrict__ codes) {
    __shared__ __align__(16) float sA[BM * SROWF];
    __shared__ __align__(16) float sB[BN * SROWF];
    __shared__ __align__(16) float sbuf[8][16 * 16];

    const int tid  = threadIdx.x;
    const int lane = tid & 31;
    const int warp = tid >> 5;
    const int wm = warp >> 1;    // 0..3 -> 32 rows each
    const int wn = warp & 1;     // 0..1 -> 64 cols each
    const int mBase  = blockIdx.x * BM;
    const int nChunk = blockIdx.y * NCHUNK;

    const int lr0  = tid >> 2;          // rows 0..63 (and +64)
    const int lseg = (tid & 3) * 8;     // elem offset 0,8,16,24

    for (int nt = 0; nt < NTILES; nt++) {
        const int nBase = nChunk + nt * BN;

        wmma::fragment<wmma::accumulator, 16, 16, 8, float> acc[2][4];
#pragma unroll
        for (int mi = 0; mi < 2; mi++)
#pragma unroll
            for (int ni = 0; ni < 4; ni++) wmma::fill_fragment(acc[mi][ni], 0.0f);

        for (int kb = 0; kb < NKSTEP; kb++) {
            const int kg = kb * BK;
            const float* ax0 = x + (size_t)(mBase + lr0) * D_ + kg + lseg;
            const float* ax1 = x + (size_t)(mBase + lr0 + 64) * D_ + kg + lseg;
            const float* bx0 = codes + (size_t)(nBase + lr0) * D_ + kg + lseg;
            const float* bx1 = codes + (size_t)(nBase + lr0 + 64) * D_ + kg + lseg;
            float4 a00 = *(const float4*)(ax0);
            float4 a01 = *(const float4*)(ax0 + 4);
            float4 a10 = *(const float4*)(ax1);
            float4 a11 = *(const float4*)(ax1 + 4);
            float4 b00 = *(const float4*)(bx0);
            float4 b01 = *(const float4*)(bx0 + 4);
            float4 b10 = *(const float4*)(bx1);
            float4 b11 = *(const float4*)(bx1 + 4);
            __syncthreads();   // previous k-step fully consumed
            *(float4*)&sA[lr0 * SROWF + lseg]            = a00;
            *(float4*)&sA[lr0 * SROWF + lseg + 4]        = a01;
            *(float4*)&sA[(lr0 + 64) * SROWF + lseg]     = a10;
            *(float4*)&sA[(lr0 + 64) * SROWF + lseg + 4] = a11;
            *(float4*)&sB[lr0 * SROWF + lseg]            = b00;
            *(float4*)&sB[lr0 * SROWF + lseg + 4]        = b01;
            *(float4*)&sB[(lr0 + 64) * SROWF + lseg]     = b10;
            *(float4*)&sB[(lr0 + 64) * SROWF + lseg + 4] = b11;
            __syncthreads();

#pragma unroll
            for (int ks = 0; ks < 4; ks++) {
                wmma::fragment<wmma::matrix_a, 16, 16, 8, wmma::precision::tf32, wmma::row_major> fa[2];
#pragma unroll
                for (int mi = 0; mi < 2; mi++) {
                    wmma::load_matrix_sync(fa[mi], &sA[(wm * 32 + mi * 16) * SROWF + ks * 8], SROWF);
#pragma unroll
                    for (int e = 0; e < fa[mi].num_elements; e++)
                        fa[mi].x[e] = wmma::__float_to_tf32(fa[mi].x[e]);
                }
#pragma unroll
                for (int ni = 0; ni < 4; ni++) {
                    // smem B is [n][k]; as a KxN matrix that's col_major with ldm=SROWF
                    wmma::fragment<wmma::matrix_b, 16, 16, 8, wmma::precision::tf32, wmma::col_major> fb;
                    wmma::load_matrix_sync(fb, &sB[(wn * 64 + ni * 16) * SROWF + ks * 8], SROWF);
#pragma unroll
                    for (int e = 0; e < fb.num_elements; e++)
                        fb.x[e] = wmma::__float_to_tf32(fb.x[e]);
                    wmma::mma_sync(acc[0][ni], fa[0], fb, acc[0][ni]);
                    wmma::mma_sync(acc[1][ni], fa[1], fb, acc[1][ni]);
                }
            }
        }

        // epilogue: drain frags (explicit indices), per-TILE min per row, nominate.
        float bestv[2];
        int   besti[2];
#pragma unroll
        for (int q = 0; q < 2; q++) { bestv[q] = __int_as_float(0x7f800000); besti[q] = nBase; }

#pragma unroll
        for (int mi = 0; mi < 2; mi++) {
#pragma unroll
            for (int ni = 0; ni < 4; ni++) {
                wmma::store_matrix_sync(&sbuf[warp][0], acc[mi][ni], 16, wmma::mem_row_major);
                __syncwarp();
                const int lr = lane >> 1;
                const int cb = (lane & 1) * 8;
                const int gcol0 = nBase + wn * 64 + ni * 16 + cb;
#pragma unroll
                for (int c = 0; c < 8; c++) {
                    float dot = sbuf[warp][lr * 16 + cb + c];
                    float s = fmaf(-2.0f, dot, g_c2[gcol0 + c]);
                    if (s < bestv[mi]) { bestv[mi] = s; besti[mi] = gcol0 + c; }
                }
                __syncwarp();
            }
        }

        const int slot = blockIdx.y * NTILES + nt;
#pragma unroll
        for (int mi = 0; mi < 2; mi++) {
            unsigned long long key =
                (((unsigned long long)float_to_ordered(bestv[mi])) << 32) | (unsigned)besti[mi];
            unsigned long long o = __shfl_xor_sync(0xffffffffu, key, 1);
            if (o < key) key = o;
            if ((lane & 1) == 0) {
                int row = mBase + wm * 32 + mi * 16 + (lane >> 1);
                atomicMin(&g_cand[(size_t)row * NCAND + slot], key);
            }
        }
    }
}

// ---------------------------------------------------------------------------
// Exact fp32 rescoring of the 128 nominees per token; emits final outputs.
// One warp per token; x row cached in registers.
// ---------------------------------------------------------------------------
__global__ __launch_bounds__(256) void refine_kernel(const float* __restrict__ x,
                                                     const float* __restrict__ codes,
                                                     float* __restrict__ out, int out_size) {
    const int t = blockIdx.x * 8 + (threadIdx.x >> 5);
    const int lane = threadIdx.x & 31;
    if (t >= MTOK) return;

    const float4* xr = (const float4*)(x + (size_t)t * D_);
    float4 xv[6];
#pragma unroll
    for (int j = 0; j < 6; j++) xv[j] = xr[lane + j * 32];

    unsigned long long best = 0xFFFFFFFFFFFFFFFFULL;

    for (int c = 0; c < NCAND; c++) {
        unsigned idx = (unsigned)(g_cand[(size_t)t * NCAND + c] & 0xffffffffu);
        if (idx >= NCODE) continue;             // unwritten/poisoned slot guard
        const float4* cr = (const float4*)(codes + (size_t)idx * D_);
        float s = 0.f;
#pragma unroll
        for (int j = 0; j < 6; j++) {
            float4 cv = cr[lane + j * 32];
            s += xv[j].x * cv.x + xv[j].y * cv.y + xv[j].z * cv.z + xv[j].w * cv.w;
        }
#pragma unroll
        for (int off = 16; off; off >>= 1) s += __shfl_xor_sync(0xffffffffu, s, off);
        float dist = fmaf(-2.0f, s, g_c2[idx]);   // exact fp32 score; inf if inactive
        unsigned long long key =
            (((unsigned long long)float_to_ordered(dist)) << 32) | (unsigned long long)idx;
        if (key < best) best = key;
    }

    if (lane == 0) {
        unsigned u = (unsigned)(best >> 32);
        unsigned b = (u & 0x80000000u) ? (u & 0x7fffffffu) : ~u;
        float s = __uint_as_float(b);
        int idx = (int)(best & 0xffffffffu);
        float dmin = g_x2[t] + s;
        int idx_out = (dmin <= THRv) ? idx : -1;
        if (best == 0xFFFFFFFFFFFFFFFFULL) { idx_out = -1; dmin = __int_as_float(0x7f800000); }
        out[t] = (float)idx_out;
        if (out_size >= 2 * MTOK) out[MTOK + t] = dmin;
    }
}

// ---------------------------------------------------------------------------
extern "C" void kernel_launch(void* const* d_in, const int* in_sizes, int n_in,
                              void* d_out, int out_size) {
    const float* x     = (const float*)d_in[0];
    const float* codes = (const float*)d_in[1];
    const unsigned char* act = (const unsigned char*)d_in[2];

    prep_c2_kernel<<<NCODE, 128>>>(codes, act);
    prep_x2_kernel<<<MTOK, 128>>>(x);
    init_cand_kernel<<<(MTOK * NCAND + 255) / 256, 256>>>();
    gemm_tf32_kernel<<<dim3(MTOK / BM, NSPLIT), 256>>>(x, codes);
    refine_kernel<<<MTOK / 8, 256>>>(x, codes, (float*)d_out, out_size);
}